// round 1
// baseline (speedup 1.0000x reference)
#include <cuda_runtime.h>
#include <math_constants.h>

// GaussianMixture: N=131072 points, K=256 clusters, D=32.
// q_ik = (x-c)^T A_k (x-c) computed as x^T A x - 2 x^T m + c^T A c with
// A = S S^T, m = A c.  Symmetric packing (diag + doubled upper-tri) halves
// the MAC count; fma.rn.f32x2 doubles fp32 throughput.

#define N_PTS 131072
#define K_CL  256
#define D_DIM 32

typedef unsigned long long u64;

__host__ __device__ constexpr int rowFe(int d) { return d & ~1; }
__host__ __device__ constexpr int rowL4(int d) { return (D_DIM - rowFe(d) + 3) & ~3; }
__host__ __device__ constexpr int rowOff(int d) {
    int o = 0;
    for (int j = 0; j < d; ++j) o += rowL4(j);
    return o;
}
constexpr int PACKED = rowOff(D_DIM);   // 576 floats per cluster

// scratch (no cudaMalloc allowed)
__device__ __align__(16) float g_P[K_CL * PACKED];   // packed quadratic-form table
__device__ __align__(16) float g_m[K_CL * D_DIM];    // m_k = A_k c_k
__device__ float g_c[K_CL];                          // log coef_k - 0.5 c^T A c

// ---- f32x2 helpers (sm_100+) ----
__device__ __forceinline__ u64 ffma2(u64 a, u64 b, u64 c) {
    u64 d;
    asm("fma.rn.f32x2 %0, %1, %2, %3;" : "=l"(d) : "l"(a), "l"(b), "l"(c));
    return d;
}
__device__ __forceinline__ u64 fadd2(u64 a, u64 b) {
    u64 d;
    asm("add.rn.f32x2 %0, %1, %2;" : "=l"(d) : "l"(a), "l"(b));
    return d;
}
__device__ __forceinline__ u64 fpack2(float lo, float hi) {
    u64 d;
    asm("mov.b64 %0, {%1, %2};" : "=l"(d) : "f"(lo), "f"(hi));
    return d;
}
__device__ __forceinline__ void funpack2(u64 v, float& lo, float& hi) {
    asm("mov.b64 {%0, %1}, %2;" : "=f"(lo), "=f"(hi) : "l"(v));
}

// ============================================================================
// Prep: per-cluster A = S S^T, packed table, m = A c, c^T A c, log|det S| via
// Cholesky of A, log-domain mixture coefficient. One block (128 thr) per k.
// ============================================================================
__global__ void __launch_bounds__(128) prep_kernel(
    const float* __restrict__ centers,
    const float* __restrict__ S_all,
    const float* __restrict__ weights)
{
    __shared__ float sS[D_DIM][D_DIM + 1];
    __shared__ float sA[D_DIM][D_DIM + 1];
    __shared__ float sCen[D_DIM];
    __shared__ float sLogSumW;
    __shared__ float sCAC;

    const int k = blockIdx.x;
    const int tid = threadIdx.x;
    const float* Sg = S_all + (size_t)k * D_DIM * D_DIM;

    for (int idx = tid; idx < D_DIM * D_DIM; idx += blockDim.x)
        sS[idx >> 5][idx & 31] = Sg[idx];
    if (tid < D_DIM) sCen[tid] = centers[k * D_DIM + tid];
    __syncthreads();

    // sum |w| (warp 0)
    if (tid < 32) {
        float s = 0.f;
        for (int j = tid; j < K_CL; j += 32) s += fabsf(weights[j]);
        #pragma unroll
        for (int off = 16; off; off >>= 1) s += __shfl_xor_sync(0xffffffffu, s, off);
        if (tid == 0) sLogSumW = logf(s + 1e-30f);
    }

    // A[d][f] = sum_e S[d][e] S[f][e]
    for (int idx = tid; idx < D_DIM * D_DIM; idx += blockDim.x) {
        int d = idx >> 5, f = idx & 31;
        float acc = 0.f;
        #pragma unroll
        for (int e = 0; e < D_DIM; ++e) acc += sS[d][e] * sS[f][e];
        sA[d][f] = acc;
    }
    __syncthreads();

    // packed table: row d holds f in [fe, fe+L4): 0 below diag / pad, A_dd on
    // diag, 2*A_df above diag.
    {
        float* Pk = g_P + (size_t)k * PACKED;
        int off = 0;
        for (int d = 0; d < D_DIM; ++d) {
            const int fe = d & ~1;
            const int L4 = (D_DIM - fe + 3) & ~3;
            for (int idx = tid; idx < L4; idx += blockDim.x) {
                const int f = fe + idx;
                float v = 0.f;
                if (f == d) v = sA[d][d];
                else if (f > d && f < D_DIM) v = 2.f * sA[d][f];
                Pk[off + idx] = v;
            }
            off += L4;
        }
    }

    // m = A c ; cAc = m . c   (warp 0, lane = d)
    if (tid < 32) {
        float md = 0.f;
        #pragma unroll
        for (int f = 0; f < D_DIM; ++f) md += sA[tid][f] * sCen[f];
        g_m[k * D_DIM + tid] = md;
        float t = md * sCen[tid];
        #pragma unroll
        for (int off = 16; off; off >>= 1) t += __shfl_xor_sync(0xffffffffu, t, off);
        if (tid == 0) sCAC = t;
    }
    __syncthreads();   // packing must finish before Cholesky clobbers sA

    // Cholesky of A (SPD) in-place, lower triangle; log sqrt(det A) = sum log L_ii
    if (tid < 32) {
        const int i = tid;
        for (int j = 0; j < D_DIM; ++j) {
            float diag = sqrtf(sA[j][j]);
            __syncwarp();
            if (i == j) sA[j][j] = diag;
            else if (i > j) sA[i][j] = sA[i][j] / diag;
            __syncwarp();
            float lij = (i > j) ? sA[i][j] : 0.f;
            for (int c = j + 1; c <= i; ++c) sA[i][c] -= lij * sA[c][j];
            __syncwarp();
        }
        float ld = logf(sA[i][i]);
        #pragma unroll
        for (int off = 16; off; off >>= 1) ld += __shfl_xor_sync(0xffffffffu, ld, off);
        if (tid == 0)
            g_c[k] = logf(fabsf(weights[k])) - sLogSumW + ld - 0.5f * sCAC;
    }
}

// ============================================================================
// Main: one thread per point; loop clusters; per cluster stage packed table
// into smem; quadratic form via f32x2 FMA; online weighted logsumexp.
// ============================================================================
__global__ void __launch_bounds__(256) gmm_kernel(
    const float* __restrict__ points,
    const float* __restrict__ threshold,
    float* __restrict__ out)
{
    __shared__ __align__(16) float sP[PACKED];
    __shared__ __align__(16) float sM[D_DIM];
    __shared__ float sC;

    const int tid = threadIdx.x;
    const int i = blockIdx.x * 256 + tid;

    // point in packed f32x2 pairs; pad pairs 16,17 with zeros (row padding
    // multiplies them by packed zeros).
    u64 xp[18];
    {
        const float4* px = (const float4*)(points + (size_t)i * D_DIM);
        #pragma unroll
        for (int r = 0; r < 8; ++r) {
            float4 v = px[r];
            xp[2 * r]     = fpack2(v.x, v.y);
            xp[2 * r + 1] = fpack2(v.z, v.w);
        }
        xp[16] = 0ull;
        xp[17] = 0ull;
    }

    float runM = -CUDART_INF_F;
    float runS = 0.f;

    for (int k = 0; k < K_CL; ++k) {
        __syncthreads();
        if (tid < PACKED / 4) {
            ((float4*)sP)[tid] = ((const float4*)(g_P + (size_t)k * PACKED))[tid];
        } else if (tid < PACKED / 4 + D_DIM / 4) {
            ((float4*)sM)[tid - PACKED / 4] =
                ((const float4*)(g_m + k * D_DIM))[tid - PACKED / 4];
        } else if (tid == PACKED / 4 + D_DIM / 4) {
            sC = g_c[k];
        }
        __syncthreads();

        // xAx = sum_d x_d * (packed_row_d . x)
        float xAx = 0.f;
        #pragma unroll
        for (int d = 0; d < D_DIM; ++d) {
            const int fe = d & ~1;
            const int nQ = ((D_DIM - fe + 3) & ~3) >> 2;
            const ulonglong2* row = (const ulonglong2*)(sP + rowOff(d));
            u64 a0 = 0ull, a1 = 0ull;
            #pragma unroll
            for (int p = 0; p < nQ; ++p) {
                ulonglong2 av = row[p];
                a0 = ffma2(av.x, xp[(fe >> 1) + 2 * p],     a0);
                a1 = ffma2(av.y, xp[(fe >> 1) + 2 * p + 1], a1);
            }
            float lo, hi;
            funpack2(fadd2(a0, a1), lo, hi);
            float xlo, xhi;
            funpack2(xp[d >> 1], xlo, xhi);
            xAx = fmaf((d & 1) ? xhi : xlo, lo + hi, xAx);
        }

        // x . m
        u64 b0 = 0ull, b1 = 0ull;
        const ulonglong2* mrow = (const ulonglong2*)sM;
        #pragma unroll
        for (int p = 0; p < 8; ++p) {
            ulonglong2 mv = mrow[p];
            b0 = ffma2(mv.x, xp[2 * p],     b0);
            b1 = ffma2(mv.y, xp[2 * p + 1], b1);
        }
        float mlo, mhi;
        funpack2(fadd2(b0, b1), mlo, mhi);

        const float v = fmaf(-0.5f, xAx, mlo + mhi) + sC;

        // online logsumexp
        const float nM = fmaxf(runM, v);
        runS = runS * __expf(runM - nM) + __expf(v - nM);
        runM = nM;
    }

    out[i] = runM + logf(runS) - threshold[0];
}

extern "C" void kernel_launch(void* const* d_in, const int* in_sizes, int n_in,
                              void* d_out, int out_size)
{
    const float* points  = (const float*)d_in[0];   // [N, 32]
    const float* centers = (const float*)d_in[1];   // [256, 32]
    const float* covs    = (const float*)d_in[2];   // [256, 32, 32]
    const float* weights = (const float*)d_in[3];   // [256]
    const float* thresh  = (const float*)d_in[4];   // [1]
    float* out = (float*)d_out;                     // [N, 1]

    prep_kernel<<<K_CL, 128>>>(centers, covs, weights);
    gmm_kernel<<<N_PTS / 256, 256>>>(points, thresh, out);
}

// round 3
// speedup vs baseline: 3.4987x; 3.4987x over previous
#include <cuda_runtime.h>
#include <cuda_fp16.h>
#include <math_constants.h>
#include <cstdint>

// GaussianMixture N=131072, K=256, D=32 via mma.sync (sm_103 baseline; no
// tcgen05 — build targets compute_103 PTX, 'a'-features unavailable).
//
// q_ik = x~^T Atil_k x~, x~=[x,1], Atil=[[A,-m],[-m^T,cAc]], A=S S^T, m=A c.
// Packed upper triangle (561 pairs, padded to 576): q = sum_p V[i][p]*C[k][p].
// fp16 3-split GEMM: Vh*Ch + Vl*Ch + Vh*Cl (fp32 accum) == fp32-accurate.
// Per CTA: 128 points x 256 clusters; 8 warps, 64x64 warp tiles; K in 9
// chunks of 64 pairs; per chunk only 2 A images (hi,lo) and 2 B images
// (hi,lo) are staged, 3 MMA passes reuse them.

#define N_PTS   131072
#define K_CL    256
#define SEC     576
#define NPC     9          // pair-chunks of 64
#define M_CTA   128
#define TPB     256

typedef unsigned long long u64;

// ---------------- device scratch ----------------
// B tiles: [img(0=hi,1=lo)][pc][256 clusters x 64 pairs fp16, 128B rows,
// XOR-swizzled] = 18 x 32KB
__device__ __align__(128) __half g_B2[18 * 16384];
__device__ int   g_kmap[SEC];
__device__ float g_logcoef[K_CL];

// ---------------- helpers ----------------
__device__ __forceinline__ uint32_t smem_u32(const void* p) {
    uint32_t a;
    asm("{ .reg .u64 t; cvta.to.shared.u64 t, %1; cvt.u32.u64 %0, t; }"
        : "=r"(a) : "l"(p));
    return a;
}
__device__ __forceinline__ uint32_t lds32(uint32_t a) {
    uint32_t v;
    asm volatile("ld.shared.b32 %0, [%1];" : "=r"(v) : "r"(a));
    return v;
}

#define MBARRIER_INIT(a, n) \
    asm volatile("mbarrier.init.shared.b64 [%0], %1;" \
                 :: "r"((uint32_t)(a)), "r"((uint32_t)(n)) : "memory")
#define MBARRIER_EXPECT_TX(a, b) \
    asm volatile("mbarrier.arrive.expect_tx.shared.b64 _, [%0], %1;" \
                 :: "r"((uint32_t)(a)), "r"((uint32_t)(b)) : "memory")
#define MBARRIER_WAIT_PARITY(mbar, parity) do {                                   \
    uint32_t _m = (uint32_t)(mbar); uint32_t _p = (uint32_t)(parity);             \
    uint32_t _done;                                                               \
    asm volatile("{\n\t.reg .pred p;\n\t"                                         \
        "mbarrier.try_wait.parity.acquire.cta.shared::cta.b64 p, [%1], %2;\n\t"   \
        "selp.b32 %0, 1, 0, p;\n\t}" : "=r"(_done) : "r"(_m), "r"(_p) : "memory");\
    if (!_done) {                                                                 \
        asm volatile("{\n\t.reg .pred P1;\n\t"                                    \
        "WAIT_LOOP_%=:\n\t"                                                       \
        "mbarrier.try_wait.parity.acquire.cta.shared::cta.b64 P1, [%0], %1, 0x989680;\n\t" \
        "@P1 bra.uni WAIT_DONE_%=;\n\t"                                           \
        "bra.uni WAIT_LOOP_%=;\n\t"                                               \
        "WAIT_DONE_%=:\n\t}" :: "r"(_m), "r"(_p) : "memory");                     \
    }                                                                             \
} while (0)

__device__ __forceinline__ void bulk_g2s(uint32_t dst, const void* src,
                                         uint32_t bytes, uint32_t mbar) {
    asm volatile(
        "cp.async.bulk.shared::cluster.global.mbarrier::complete_tx::bytes "
        "[%0], [%1], %2, [%3];"
        :: "r"(dst), "l"(src), "r"(bytes), "r"(mbar) : "memory");
}

__device__ __forceinline__ void unrank_pair(int p, int& d, int& f) {
    int dd = 0;
    while (true) {
        int len = 33 - dd;
        if (p < len) { d = dd; f = dd + p; return; }
        p -= len; ++dd;
    }
}

// ============================================================================
// Prep: per-cluster A=SS^T, m=Ac, cAc, Cholesky logdet, logcoef, swizzled
// fp16 hi/lo B tiles. One block per cluster.
// ============================================================================
__global__ void __launch_bounds__(128) prep_kernel(
    const float* __restrict__ centers,
    const float* __restrict__ S_all,
    const float* __restrict__ weights)
{
    __shared__ float sS[32][33];
    __shared__ float sA[32][33];
    __shared__ float sCen[32];
    __shared__ float sM[32];
    __shared__ float sLogSumW, sCAC;

    const int k = blockIdx.x;
    const int tid = threadIdx.x;
    const float* Sg = S_all + (size_t)k * 1024;

    for (int i = tid; i < 1024; i += 128) sS[i >> 5][i & 31] = Sg[i];
    if (tid < 32) sCen[tid] = centers[k * 32 + tid];
    __syncthreads();

    if (tid < 32) {
        float s = 0.f;
        for (int j = tid; j < K_CL; j += 32) s += fabsf(weights[j]);
        #pragma unroll
        for (int o = 16; o; o >>= 1) s += __shfl_xor_sync(0xffffffffu, s, o);
        if (tid == 0) sLogSumW = logf(s + 1e-30f);
    }

    for (int i = tid; i < 1024; i += 128) {
        int d = i >> 5, f = i & 31;
        float acc = 0.f;
        #pragma unroll
        for (int e = 0; e < 32; ++e) acc += sS[d][e] * sS[f][e];
        sA[d][f] = acc;
    }
    __syncthreads();

    if (tid < 32) {
        float md = 0.f;
        #pragma unroll
        for (int f = 0; f < 32; ++f) md += sA[tid][f] * sCen[f];
        sM[tid] = md;
        float t = md * sCen[tid];
        #pragma unroll
        for (int o = 16; o; o >>= 1) t += __shfl_xor_sync(0xffffffffu, t, o);
        if (tid == 0) sCAC = t;
    }
    __syncthreads();

    // B tiles (hi & lo), swizzled 128B rows: raw = k*128 + (p&63)*2
    for (int p = tid; p < SEC; p += 128) {
        float coef = 0.f;
        if (p < 561) {
            int d, f; unrank_pair(p, d, f);
            if (f < 32)      coef = (d == f) ? sA[d][d] : 2.f * sA[d][f];
            else if (d < 32) coef = -2.f * sM[d];
            else             coef = sCAC;
        }
        __half ch = __float2half_rn(coef);
        __half cl = __float2half_rn(coef - __half2float(ch));
        const int pc = p >> 6, kl = p & 63;
        uint32_t raw = (uint32_t)(k * 128 + kl * 2);
        uint32_t swz = raw ^ ((raw >> 3) & 0x70);
        *(__half*)((char*)g_B2 + (size_t)pc * 32768 + swz) = ch;
        *(__half*)((char*)g_B2 + (size_t)(9 + pc) * 32768 + swz) = cl;
    }
    __syncthreads();

    // Cholesky of A (clobbers sA), warp 0
    if (tid < 32) {
        const int i = tid;
        for (int j = 0; j < 32; ++j) {
            float diag = sqrtf(sA[j][j]);
            __syncwarp();
            if (i == j) sA[j][j] = diag;
            else if (i > j) sA[i][j] = sA[i][j] / diag;
            __syncwarp();
            float lij = (i > j) ? sA[i][j] : 0.f;
            for (int c = j + 1; c <= i; ++c) sA[i][c] -= lij * sA[c][j];
            __syncwarp();
        }
        float ld = logf(sA[i][i]);
        #pragma unroll
        for (int o = 16; o; o >>= 1) ld += __shfl_xor_sync(0xffffffffu, ld, o);
        if (tid == 0)
            g_logcoef[k] = logf(fabsf(weights[k])) - sLogSumW + ld;
    }

    if (blockIdx.x == 0) {
        for (int p = tid; p < SEC; p += 128) {
            int d = 0, f = 0;
            if (p < 561) unrank_pair(p, d, f);
            g_kmap[p] = d | (f << 8);
        }
    }
}

// ============================================================================
// Main kernel
// ============================================================================
// dynamic smem layout (bytes from 1024-aligned base):
#define OFF_A    0u         // 4 A tiles (buf*2+img)*16384  -> 65536
#define OFF_B    65536u     // 4 B tiles (buf*2+img)*32768  -> +131072
#define OFF_X    196608u    // 128*33*4 = 16896
#define OFF_KM   213504u    // 576*4
#define OFF_LOG  215808u    // 256*4
#define OFF_RED  216832u    // 128*4 float2 = 4096
#define OFF_BAR  220928u    // 2 mbarriers
#define SMEM_END 220944u
#define SMEM_BYTES (SMEM_END + 1024u)

__device__ __forceinline__ void build_a_tiles(
    const float* __restrict__ px, const int* __restrict__ sKm,
    int pc, int h, char* aHi, char* aLo, int p)
{
    const int pbase = pc * 64 + h * 32;
    const int rowbyte = p * 128;
    const int msk = (p & 7) << 4;
    #pragma unroll
    for (int g = 0; g < 4; ++g) {
        uint32_t wh[4], wl[4];
        #pragma unroll
        for (int q = 0; q < 4; ++q) {
            unsigned short hs[2], ls[2];
            #pragma unroll
            for (int e = 0; e < 2; ++e) {
                const int mp = sKm[pbase + g * 8 + q * 2 + e];
                const float v = px[mp & 255] * px[mp >> 8];
                const __half hi = __float2half_rn(v);
                const __half lo = __float2half_rn(v - __half2float(hi));
                hs[e] = __half_as_ushort(hi);
                ls[e] = __half_as_ushort(lo);
            }
            wh[q] = (uint32_t)hs[0] | ((uint32_t)hs[1] << 16);
            wl[q] = (uint32_t)ls[0] | ((uint32_t)ls[1] << 16);
        }
        const int off = rowbyte + ((h * 64 + g * 16) ^ msk);
        *(uint4*)(aHi + off) = make_uint4(wh[0], wh[1], wh[2], wh[3]);
        *(uint4*)(aLo + off) = make_uint4(wl[0], wl[1], wl[2], wl[3]);
    }
}

__device__ __forceinline__ void mma_pass(
    uint32_t aT, uint32_t bT, float (&acc)[4][8][4],
    int gid, int tig, int warpM, int warpN)
{
    const int msk = gid << 4;
    #pragma unroll
    for (int ks = 0; ks < 4; ++ks) {
        const int c0 = (ks * 16 + tig * 2) * 2;
        const int cA0 = c0 ^ msk;
        const int cA1 = (c0 + 16) ^ msk;
        uint32_t a[4][4];
        #pragma unroll
        for (int m = 0; m < 4; ++m) {
            const uint32_t r0 = aT + (uint32_t)((warpM * 64 + m * 16 + gid) * 128);
            a[m][0] = lds32(r0 + cA0);
            a[m][1] = lds32(r0 + 1024 + cA0);
            a[m][2] = lds32(r0 + cA1);
            a[m][3] = lds32(r0 + 1024 + cA1);
        }
        uint32_t b[8][2];
        #pragma unroll
        for (int n = 0; n < 8; ++n) {
            const uint32_t rb = bT + (uint32_t)((warpN * 64 + n * 8 + gid) * 128);
            b[n][0] = lds32(rb + cA0);
            b[n][1] = lds32(rb + cA1);
        }
        #pragma unroll
        for (int m = 0; m < 4; ++m)
            #pragma unroll
            for (int n = 0; n < 8; ++n)
                asm volatile(
                    "mma.sync.aligned.m16n8k16.row.col.f32.f16.f16.f32 "
                    "{%0,%1,%2,%3}, {%4,%5,%6,%7}, {%8,%9}, {%0,%1,%2,%3};"
                    : "+f"(acc[m][n][0]), "+f"(acc[m][n][1]),
                      "+f"(acc[m][n][2]), "+f"(acc[m][n][3])
                    : "r"(a[m][0]), "r"(a[m][1]), "r"(a[m][2]), "r"(a[m][3]),
                      "r"(b[n][0]), "r"(b[n][1]));
    }
}

__global__ void __launch_bounds__(TPB, 1)
gmm_mma_kernel(const float* __restrict__ points,
               const float* __restrict__ threshold,
               float* __restrict__ out)
{
    extern __shared__ char dsm[];
    const uint32_t rawb = smem_u32(dsm);
    const uint32_t base = (rawb + 1023u) & ~1023u;
    char* bp = dsm + (base - rawb);

    float* sX   = (float*)(bp + OFF_X);
    int*   sKm  = (int*)(bp + OFF_KM);
    float* sLog = (float*)(bp + OFF_LOG);
    float2* sRed = (float2*)(bp + OFF_RED);

    const int tid = threadIdx.x;
    const int wid = tid >> 5;
    const int lane = tid & 31;
    const int gid = lane >> 2;
    const int tig = lane & 3;
    const int warpM = wid >> 2;
    const int warpN = wid & 3;
    const int p = tid & 127;     // A-build: point row
    const int h = tid >> 7;      // A-build: which 32-pair half

    // ---- init loads ----
    for (int i = tid; i < SEC; i += TPB) sKm[i] = g_kmap[i];
    if (tid < K_CL) sLog[tid] = g_logcoef[tid];
    {
        const float4* src = (const float4*)(points +
            ((size_t)blockIdx.x * M_CTA + p) * 32 + h * 16);
        float* xr = sX + p * 33;
        #pragma unroll
        for (int r = 0; r < 4; ++r) {
            float4 v = src[r];
            xr[h * 16 + 4 * r] = v.x; xr[h * 16 + 4 * r + 1] = v.y;
            xr[h * 16 + 4 * r + 2] = v.z; xr[h * 16 + 4 * r + 3] = v.w;
        }
        if (h == 0) xr[32] = 1.0f;
    }

    const uint32_t bar[2] = { base + OFF_BAR, base + OFF_BAR + 8u };
    if (tid == 0) { MBARRIER_INIT(bar[0], 1); MBARRIER_INIT(bar[1], 1); }
    __syncthreads();

    const float* px = sX + p * 33;
    float acc[4][8][4];
    #pragma unroll
    for (int m = 0; m < 4; ++m)
        #pragma unroll
        for (int n = 0; n < 8; ++n)
            #pragma unroll
            for (int e = 0; e < 4; ++e) acc[m][n][e] = 0.f;

    // prologue: stage pc=0 into buf 0
    if (tid == 0) {
        MBARRIER_EXPECT_TX(bar[0], 65536u);
        bulk_g2s(base + OFF_B + 0u,      (const char*)g_B2,                32768u, bar[0]);
        bulk_g2s(base + OFF_B + 32768u,  (const char*)g_B2 + 9u * 32768u,  32768u, bar[0]);
    }
    build_a_tiles(px, sKm, 0, h, bp + OFF_A, bp + OFF_A + 16384u, p);

    int ph[2] = { 0, 0 };

    for (int pc = 0; pc < NPC; ++pc) {
        const int buf = pc & 1, nb = buf ^ 1;
        if (pc + 1 < NPC) {
            build_a_tiles(px, sKm, pc + 1, h,
                          bp + OFF_A + (uint32_t)nb * 32768u,
                          bp + OFF_A + (uint32_t)nb * 32768u + 16384u, p);
            if (tid == 0) {
                MBARRIER_EXPECT_TX(bar[nb], 65536u);
                bulk_g2s(base + OFF_B + (uint32_t)nb * 65536u,
                         (const char*)g_B2 + (size_t)(pc + 1) * 32768u,
                         32768u, bar[nb]);
                bulk_g2s(base + OFF_B + (uint32_t)nb * 65536u + 32768u,
                         (const char*)g_B2 + (size_t)(9 + pc + 1) * 32768u,
                         32768u, bar[nb]);
            }
        }
        MBARRIER_WAIT_PARITY(bar[buf], ph[buf]);
        ph[buf] ^= 1;
        __syncthreads();

        const uint32_t aHiT = base + OFF_A + (uint32_t)buf * 32768u;
        const uint32_t aLoT = aHiT + 16384u;
        const uint32_t bHiT = base + OFF_B + (uint32_t)buf * 65536u;
        const uint32_t bLoT = bHiT + 32768u;

        mma_pass(aHiT, bHiT, acc, gid, tig, warpM, warpN);
        mma_pass(aLoT, bHiT, acc, gid, tig, warpM, warpN);
        mma_pass(aHiT, bLoT, acc, gid, tig, warpM, warpN);

        __syncthreads();
    }

    // ---- epilogue: weighted logsumexp ----
    float lc[8][2];
    #pragma unroll
    for (int n = 0; n < 8; ++n) {
        lc[n][0] = sLog[warpN * 64 + n * 8 + tig * 2];
        lc[n][1] = sLog[warpN * 64 + n * 8 + tig * 2 + 1];
    }

    #pragma unroll
    for (int m = 0; m < 4; ++m) {
        #pragma unroll
        for (int rr = 0; rr < 2; ++rr) {
            float mx = -CUDART_INF_F, ss = 0.f;
            #pragma unroll
            for (int n = 0; n < 8; ++n) {
                #pragma unroll
                for (int e = 0; e < 2; ++e) {
                    const float v = fmaf(-0.5f, acc[m][n][rr * 2 + e], lc[n][e]);
                    const float nm = fmaxf(mx, v);
                    ss = ss * __expf(mx - nm) + __expf(v - nm);
                    mx = nm;
                }
            }
            #pragma unroll
            for (int off = 1; off <= 2; off <<= 1) {
                const float om = __shfl_xor_sync(0xffffffffu, mx, off);
                const float os = __shfl_xor_sync(0xffffffffu, ss, off);
                const float nm = fmaxf(mx, om);
                ss = ss * __expf(mx - nm) + os * __expf(om - nm);
                mx = nm;
            }
            if (tig == 0) {
                const int row = warpM * 64 + m * 16 + rr * 8 + gid;
                sRed[row * 4 + warpN] = make_float2(mx, ss);
            }
        }
    }
    __syncthreads();

    if (tid < M_CTA) {
        float2 v = sRed[tid * 4];
        float mx = v.x, ss = v.y;
        #pragma unroll
        for (int w = 1; w < 4; ++w) {
            const float2 o = sRed[tid * 4 + w];
            const float nm = fmaxf(mx, o.x);
            ss = ss * __expf(mx - nm) + o.y * __expf(o.x - nm);
            mx = nm;
        }
        out[(size_t)blockIdx.x * M_CTA + tid] = mx + logf(ss) - threshold[0];
    }
}

extern "C" void kernel_launch(void* const* d_in, const int* in_sizes, int n_in,
                              void* d_out, int out_size)
{
    const float* points  = (const float*)d_in[0];
    const float* centers = (const float*)d_in[1];
    const float* covs    = (const float*)d_in[2];
    const float* weights = (const float*)d_in[3];
    const float* thresh  = (const float*)d_in[4];
    float* out = (float*)d_out;

    cudaFuncSetAttribute(gmm_mma_kernel,
                         cudaFuncAttributeMaxDynamicSharedMemorySize, SMEM_BYTES);

    prep_kernel<<<K_CL, 128>>>(centers, covs, weights);
    gmm_mma_kernel<<<N_PTS / M_CTA, TPB, SMEM_BYTES>>>(points, thresh, out);
}

// round 4
// speedup vs baseline: 4.0741x; 1.1645x over previous
#include <cuda_runtime.h>
#include <cuda_fp16.h>
#include <math_constants.h>
#include <cstdint>

// GaussianMixture N=131072, K=256, D=32 via mma.sync (sm_103 baseline).
// q_ik = x~^T Atil_k x~ over 561 packed upper-tri pairs (pad to 576).
// fp16 3-split GEMM: Vh*Ch + Vl*Ch + Vh*Cl, fp32 accum.
// Round 4: ldmatrix fragment loads, fused per-ks 3-pass, overlapped
// A-build/TMA behind the HMMA stream.

#define N_PTS   131072
#define K_CL    256
#define SEC     576
#define NPC     9
#define M_CTA   128
#define TPB     256

typedef unsigned long long u64;

// B tiles: [pc][img(hi,lo)][256 clusters x 64 pairs fp16, 128B swizzled rows]
__device__ __align__(128) __half g_B2[NPC * 2 * 16384];
__device__ int   g_kmap[SEC];
__device__ float g_logcoef[K_CL];

// ---------------- helpers ----------------
__device__ __forceinline__ uint32_t smem_u32(const void* p) {
    uint32_t a;
    asm("{ .reg .u64 t; cvta.to.shared.u64 t, %1; cvt.u32.u64 %0, t; }"
        : "=r"(a) : "l"(p));
    return a;
}
__device__ __forceinline__ void ldsm_x4(uint32_t r[4], uint32_t addr) {
    asm volatile("ldmatrix.sync.aligned.m8n8.x4.shared.b16 {%0,%1,%2,%3}, [%4];"
        : "=r"(r[0]), "=r"(r[1]), "=r"(r[2]), "=r"(r[3]) : "r"(addr));
}

#define MBARRIER_INIT(a, n) \
    asm volatile("mbarrier.init.shared.b64 [%0], %1;" \
                 :: "r"((uint32_t)(a)), "r"((uint32_t)(n)) : "memory")
#define MBARRIER_EXPECT_TX(a, b) \
    asm volatile("mbarrier.arrive.expect_tx.shared.b64 _, [%0], %1;" \
                 :: "r"((uint32_t)(a)), "r"((uint32_t)(b)) : "memory")
#define MBARRIER_WAIT_PARITY(mbar, parity) do {                                   \
    uint32_t _m = (uint32_t)(mbar); uint32_t _p = (uint32_t)(parity);             \
    uint32_t _done;                                                               \
    asm volatile("{\n\t.reg .pred p;\n\t"                                         \
        "mbarrier.try_wait.parity.acquire.cta.shared::cta.b64 p, [%1], %2;\n\t"   \
        "selp.b32 %0, 1, 0, p;\n\t}" : "=r"(_done) : "r"(_m), "r"(_p) : "memory");\
    if (!_done) {                                                                 \
        asm volatile("{\n\t.reg .pred P1;\n\t"                                    \
        "WAIT_LOOP_%=:\n\t"                                                       \
        "mbarrier.try_wait.parity.acquire.cta.shared::cta.b64 P1, [%0], %1, 0x989680;\n\t" \
        "@P1 bra.uni WAIT_DONE_%=;\n\t"                                           \
        "bra.uni WAIT_LOOP_%=;\n\t"                                               \
        "WAIT_DONE_%=:\n\t}" :: "r"(_m), "r"(_p) : "memory");                     \
    }                                                                             \
} while (0)

__device__ __forceinline__ void bulk_g2s(uint32_t dst, const void* src,
                                         uint32_t bytes, uint32_t mbar) {
    asm volatile(
        "cp.async.bulk.shared::cluster.global.mbarrier::complete_tx::bytes "
        "[%0], [%1], %2, [%3];"
        :: "r"(dst), "l"(src), "r"(bytes), "r"(mbar) : "memory");
}

__device__ __forceinline__ void unrank_pair(int p, int& d, int& f) {
    int dd = 0;
    while (true) {
        int len = 33 - dd;
        if (p < len) { d = dd; f = dd + p; return; }
        p -= len; ++dd;
    }
}

// ============================================================================
// Prep (one block per cluster)
// ============================================================================
__global__ void __launch_bounds__(128) prep_kernel(
    const float* __restrict__ centers,
    const float* __restrict__ S_all,
    const float* __restrict__ weights)
{
    __shared__ float sS[32][33];
    __shared__ float sA[32][33];
    __shared__ float sCen[32];
    __shared__ float sM[32];
    __shared__ float sLogSumW, sCAC;

    const int k = blockIdx.x;
    const int tid = threadIdx.x;
    const float* Sg = S_all + (size_t)k * 1024;

    for (int i = tid; i < 1024; i += 128) sS[i >> 5][i & 31] = Sg[i];
    if (tid < 32) sCen[tid] = centers[k * 32 + tid];
    __syncthreads();

    if (tid < 32) {
        float s = 0.f;
        for (int j = tid; j < K_CL; j += 32) s += fabsf(weights[j]);
        #pragma unroll
        for (int o = 16; o; o >>= 1) s += __shfl_xor_sync(0xffffffffu, s, o);
        if (tid == 0) sLogSumW = logf(s + 1e-30f);
    }

    for (int i = tid; i < 1024; i += 128) {
        int d = i >> 5, f = i & 31;
        float acc = 0.f;
        #pragma unroll
        for (int e = 0; e < 32; ++e) acc += sS[d][e] * sS[f][e];
        sA[d][f] = acc;
    }
    __syncthreads();

    if (tid < 32) {
        float md = 0.f;
        #pragma unroll
        for (int f = 0; f < 32; ++f) md += sA[tid][f] * sCen[f];
        sM[tid] = md;
        float t = md * sCen[tid];
        #pragma unroll
        for (int o = 16; o; o >>= 1) t += __shfl_xor_sync(0xffffffffu, t, o);
        if (tid == 0) sCAC = t;
    }
    __syncthreads();

    // B images per chunk: [pc][hi 32KB | lo 32KB], swizzled 128B rows.
    for (int p = tid; p < SEC; p += 128) {
        float coef = 0.f;
        if (p < 561) {
            int d, f; unrank_pair(p, d, f);
            if (f < 32)      coef = (d == f) ? sA[d][d] : 2.f * sA[d][f];
            else if (d < 32) coef = -2.f * sM[d];
            else             coef = sCAC;
        }
        __half ch = __float2half_rn(coef);
        __half cl = __float2half_rn(coef - __half2float(ch));
        const int pc = p >> 6, kl = p & 63;
        uint32_t raw = (uint32_t)(k * 128 + kl * 2);
        uint32_t swz = raw ^ ((raw >> 3) & 0x70);
        *(__half*)((char*)g_B2 + (size_t)pc * 65536 + swz) = ch;
        *(__half*)((char*)g_B2 + (size_t)pc * 65536 + 32768 + swz) = cl;
    }
    __syncthreads();

    if (tid < 32) {
        const int i = tid;
        for (int j = 0; j < 32; ++j) {
            float diag = sqrtf(sA[j][j]);
            __syncwarp();
            if (i == j) sA[j][j] = diag;
            else if (i > j) sA[i][j] = sA[i][j] / diag;
            __syncwarp();
            float lij = (i > j) ? sA[i][j] : 0.f;
            for (int c = j + 1; c <= i; ++c) sA[i][c] -= lij * sA[c][j];
            __syncwarp();
        }
        float ld = logf(sA[i][i]);
        #pragma unroll
        for (int o = 16; o; o >>= 1) ld += __shfl_xor_sync(0xffffffffu, ld, o);
        if (tid == 0)
            g_logcoef[k] = logf(fabsf(weights[k])) - sLogSumW + ld;
    }

    if (blockIdx.x == 0) {
        for (int p = tid; p < SEC; p += 128) {
            int d = 0, f = 0;
            if (p < 561) unrank_pair(p, d, f);
            g_kmap[p] = d | (f << 8);
        }
    }
}

// ============================================================================
// Main kernel
// ============================================================================
#define OFF_A    0u         // 2 buf x [hi 16K | lo 16K]
#define OFF_B    65536u     // 2 buf x [hi 32K | lo 32K]
#define OFF_X    196608u    // 128*33*4
#define OFF_KM   213504u    // 576*4
#define OFF_LOG  215808u    // 256*4
#define OFF_RED  216832u    // 128*4 float2
#define OFF_BAR  220928u
#define SMEM_END 220944u
#define SMEM_BYTES (SMEM_END + 1024u)

__device__ __forceinline__ void build_a_tiles(
    const float* __restrict__ px, const int* __restrict__ sKm,
    int pc, int h, char* aHi, char* aLo, int p)
{
    const int pbase = pc * 64 + h * 32;
    const int rowbyte = p * 128;
    const int msk = (p & 7) << 4;
    #pragma unroll
    for (int g = 0; g < 4; ++g) {
        uint32_t wh[4], wl[4];
        #pragma unroll
        for (int q = 0; q < 4; ++q) {
            unsigned short hs[2], ls[2];
            #pragma unroll
            for (int e = 0; e < 2; ++e) {
                const int mp = sKm[pbase + g * 8 + q * 2 + e];
                const float v = px[mp & 255] * px[mp >> 8];
                const __half hi = __float2half_rn(v);
                const __half lo = __float2half_rn(v - __half2float(hi));
                hs[e] = __half_as_ushort(hi);
                ls[e] = __half_as_ushort(lo);
            }
            wh[q] = (uint32_t)hs[0] | ((uint32_t)hs[1] << 16);
            wl[q] = (uint32_t)ls[0] | ((uint32_t)ls[1] << 16);
        }
        const int off = rowbyte + ((h * 64 + g * 16) ^ msk);
        *(uint4*)(aHi + off) = make_uint4(wh[0], wh[1], wh[2], wh[3]);
        *(uint4*)(aLo + off) = make_uint4(wl[0], wl[1], wl[2], wl[3]);
    }
}

__device__ __forceinline__ void hmma_all(
    float (&acc)[4][8][4], const uint32_t (&a)[4][4], const uint32_t (&b)[4][4])
{
    #pragma unroll
    for (int mt = 0; mt < 4; ++mt)
        #pragma unroll
        for (int j = 0; j < 8; ++j) {
            const uint32_t b0 = b[j >> 1][(j & 1) * 2];
            const uint32_t b1 = b[j >> 1][(j & 1) * 2 + 1];
            asm volatile(
                "mma.sync.aligned.m16n8k16.row.col.f32.f16.f16.f32 "
                "{%0,%1,%2,%3}, {%4,%5,%6,%7}, {%8,%9}, {%0,%1,%2,%3};"
                : "+f"(acc[mt][j][0]), "+f"(acc[mt][j][1]),
                  "+f"(acc[mt][j][2]), "+f"(acc[mt][j][3])
                : "r"(a[mt][0]), "r"(a[mt][1]), "r"(a[mt][2]), "r"(a[mt][3]),
                  "r"(b0), "r"(b1));
        }
}

// Fused chunk: per ks load aHi/bHi/aLo/bLo fragments once, 3 HMMA passes.
__device__ __forceinline__ void mma_chunk(
    uint32_t aHiT, uint32_t bHiT, float (&acc)[4][8][4],
    int lane, int warpM, int warpN)
{
    const uint32_t aLoT = aHiT + 16384u;
    const uint32_t bLoT = bHiT + 32768u;

    const int rowA = (lane & 7) + ((lane >> 3) & 1) * 8;  // tile-row within 16
    const int khA  = (lane >> 4) & 1;                     // k half
    const int rowB = (lane & 7) + ((lane >> 4) & 1) * 8;
    const int khB  = (lane >> 3) & 1;
    const int sm   = (lane & 7) << 4;                     // swizzle mask

    uint32_t aBase[4], bBase[4];
    #pragma unroll
    for (int mt = 0; mt < 4; ++mt)
        aBase[mt] = (uint32_t)((warpM * 64 + mt * 16 + rowA) * 128);
    #pragma unroll
    for (int nt = 0; nt < 4; ++nt)
        bBase[nt] = (uint32_t)((warpN * 64 + nt * 16 + rowB) * 128);

    #pragma unroll
    for (int ks = 0; ks < 4; ++ks) {
        const uint32_t colA = (uint32_t)((ks * 32 + khA * 16) ^ sm);
        const uint32_t colB = (uint32_t)((ks * 32 + khB * 16) ^ sm);

        uint32_t aH[4][4], aL[4][4], bb[4][4];
        #pragma unroll
        for (int mt = 0; mt < 4; ++mt) ldsm_x4(aH[mt], aHiT + aBase[mt] + colA);
        #pragma unroll
        for (int nt = 0; nt < 4; ++nt) ldsm_x4(bb[nt], bHiT + bBase[nt] + colB);
        hmma_all(acc, aH, bb);                       // hi * hi

        #pragma unroll
        for (int mt = 0; mt < 4; ++mt) ldsm_x4(aL[mt], aLoT + aBase[mt] + colA);
        hmma_all(acc, aL, bb);                       // lo * hi

        #pragma unroll
        for (int nt = 0; nt < 4; ++nt) ldsm_x4(bb[nt], bLoT + bBase[nt] + colB);
        hmma_all(acc, aH, bb);                       // hi * lo
    }
}

__global__ void __launch_bounds__(TPB, 1)
gmm_mma_kernel(const float* __restrict__ points,
               const float* __restrict__ threshold,
               float* __restrict__ out)
{
    extern __shared__ char dsm[];
    const uint32_t rawb = smem_u32(dsm);
    const uint32_t base = (rawb + 1023u) & ~1023u;
    char* bp = dsm + (base - rawb);

    float* sX    = (float*)(bp + OFF_X);
    int*   sKm   = (int*)(bp + OFF_KM);
    float* sLog  = (float*)(bp + OFF_LOG);
    float2* sRed = (float2*)(bp + OFF_RED);

    const int tid = threadIdx.x;
    const int wid = tid >> 5;
    const int lane = tid & 31;
    const int gid = lane >> 2;
    const int tig = lane & 3;
    const int warpM = wid >> 2;
    const int warpN = wid & 3;
    const int p = tid & 127;
    const int h = tid >> 7;

    for (int i = tid; i < SEC; i += TPB) sKm[i] = g_kmap[i];
    if (tid < K_CL) sLog[tid] = g_logcoef[tid];
    {
        const float4* src = (const float4*)(points +
            ((size_t)blockIdx.x * M_CTA + p) * 32 + h * 16);
        float* xr = sX + p * 33;
        #pragma unroll
        for (int r = 0; r < 4; ++r) {
            float4 v = src[r];
            xr[h * 16 + 4 * r] = v.x; xr[h * 16 + 4 * r + 1] = v.y;
            xr[h * 16 + 4 * r + 2] = v.z; xr[h * 16 + 4 * r + 3] = v.w;
        }
        if (h == 0) xr[32] = 1.0f;
    }

    const uint32_t bar[2] = { base + OFF_BAR, base + OFF_BAR + 8u };
    if (tid == 0) { MBARRIER_INIT(bar[0], 1); MBARRIER_INIT(bar[1], 1); }
    __syncthreads();

    const float* px = sX + p * 33;
    float acc[4][8][4];
    #pragma unroll
    for (int m = 0; m < 4; ++m)
        #pragma unroll
        for (int n = 0; n < 8; ++n)
            #pragma unroll
            for (int e = 0; e < 4; ++e) acc[m][n][e] = 0.f;

    // prologue: B chunk 0 + A chunk 0
    if (tid == 0) {
        MBARRIER_EXPECT_TX(bar[0], 65536u);
        bulk_g2s(base + OFF_B, (const char*)g_B2, 65536u, bar[0]);
    }
    build_a_tiles(px, sKm, 0, h, bp + OFF_A, bp + OFF_A + 16384u, p);

    int phv[2] = { 0, 0 };
    for (int pc = 0; pc < NPC; ++pc) {
        const int buf = pc & 1, nb = buf ^ 1;
        MBARRIER_WAIT_PARITY(bar[buf], phv[buf]);
        phv[buf] ^= 1;
        __syncthreads();   // A[buf] built by all; B[buf] arrived; B/A[nb] free

        if (pc + 1 < NPC && tid == 0) {
            MBARRIER_EXPECT_TX(bar[nb], 65536u);
            bulk_g2s(base + OFF_B + (uint32_t)nb * 65536u,
                     (const char*)g_B2 + (size_t)(pc + 1) * 65536u,
                     65536u, bar[nb]);
        }

        mma_chunk(base + OFF_A + (uint32_t)buf * 32768u,
                  base + OFF_B + (uint32_t)buf * 65536u,
                  acc, lane, warpM, warpN);

        if (pc + 1 < NPC)
            build_a_tiles(px, sKm, pc + 1, h,
                          bp + OFF_A + (uint32_t)nb * 32768u,
                          bp + OFF_A + (uint32_t)nb * 32768u + 16384u, p);
    }

    // ---- epilogue: weighted logsumexp ----
    float lc[8][2];
    #pragma unroll
    for (int n = 0; n < 8; ++n) {
        lc[n][0] = sLog[warpN * 64 + n * 8 + tig * 2];
        lc[n][1] = sLog[warpN * 64 + n * 8 + tig * 2 + 1];
    }

    #pragma unroll
    for (int m = 0; m < 4; ++m) {
        #pragma unroll
        for (int rr = 0; rr < 2; ++rr) {
            float mx = -CUDART_INF_F, ss = 0.f;
            #pragma unroll
            for (int n = 0; n < 8; ++n) {
                #pragma unroll
                for (int e = 0; e < 2; ++e) {
                    const float v = fmaf(-0.5f, acc[m][n][rr * 2 + e], lc[n][e]);
                    const float nm = fmaxf(mx, v);
                    ss = ss * __expf(mx - nm) + __expf(v - nm);
                    mx = nm;
                }
            }
            #pragma unroll
            for (int off = 1; off <= 2; off <<= 1) {
                const float om = __shfl_xor_sync(0xffffffffu, mx, off);
                const float os = __shfl_xor_sync(0xffffffffu, ss, off);
                const float nm = fmaxf(mx, om);
                ss = ss * __expf(mx - nm) + os * __expf(om - nm);
                mx = nm;
            }
            if (tig == 0) {
                const int row = warpM * 64 + m * 16 + rr * 8 + gid;
                sRed[row * 4 + warpN] = make_float2(mx, ss);
            }
        }
    }
    __syncthreads();

    if (tid < M_CTA) {
        float2 v = sRed[tid * 4];
        float mx = v.x, ss = v.y;
        #pragma unroll
        for (int w = 1; w < 4; ++w) {
            const float2 o = sRed[tid * 4 + w];
            const float nm = fmaxf(mx, o.x);
            ss = ss * __expf(mx - nm) + o.y * __expf(o.x - nm);
            mx = nm;
        }
        out[(size_t)blockIdx.x * M_CTA + tid] = mx + logf(ss) - threshold[0];
    }
}

extern "C" void kernel_launch(void* const* d_in, const int* in_sizes, int n_in,
                              void* d_out, int out_size)
{
    const float* points  = (const float*)d_in[0];
    const float* centers = (const float*)d_in[1];
    const float* covs    = (const float*)d_in[2];
    const float* weights = (const float*)d_in[3];
    const float* thresh  = (const float*)d_in[4];
    float* out = (float*)d_out;

    cudaFuncSetAttribute(gmm_mma_kernel,
                         cudaFuncAttributeMaxDynamicSharedMemorySize, SMEM_BYTES);

    prep_kernel<<<K_CL, 128>>>(centers, covs, weights);
    gmm_mma_kernel<<<N_PTS / M_CTA, TPB, SMEM_BYTES>>>(points, thresh, out);
}